// round 1
// baseline (speedup 1.0000x reference)
#include <cuda_runtime.h>

#define WSZ 64      // window / block size
#define D   64      // head dim

// SMEM layout (floats):
//   sM   [128]            mask window (0/1)
//   sQt  [64][68]         Q transposed: [dd][i], scaled by 1/8
//   sKtP [64][132]        K transposed: [dd][m]; ALIASED later as sP[i][132] (probs)
//   sV   [128][64]        V straight: [m][dd]
// total = 128 + 64*68 + 64*132 + 128*64 = 21120 floats = 84480 bytes

__global__ __launch_bounds__(256, 2)
void lca_kernel(const float* __restrict__ q, const float* __restrict__ k,
                const float* __restrict__ v, const int* __restrict__ mask,
                float* __restrict__ out, int T, int H)
{
    extern __shared__ float sm[];
    float* sM  = sm;                    // 128
    float* sQt = sm + 128;              // 64*68
    float* sKt = sQt + 64 * 68;         // 64*132
    float* sP  = sKt;                   // alias (K dead after QK)
    float* sV  = sKt + 64 * 132;        // 128*64

    const int j   = blockIdx.x;         // key/query block
    const int h   = blockIdx.y;
    const int b   = blockIdx.z;
    const int tid = threadIdx.x;
    const int tx  = tid & 15;           // 0..15
    const int ty  = tid >> 4;           // 0..15

    const long rowstride = (long)H * D;                    // floats per token
    const long bbase     = (long)b * T * rowstride;
    const int  q0        = j * WSZ;                        // first query index

    // ---- mask window: sM[m] = mask at key global index q0 + m - 64 (0 if OOB)
    if (tid < 128) {
        int kg = q0 + tid - WSZ;
        sM[tid] = (kg >= 0) ? (float)mask[(long)b * T + kg] : 0.0f;
    }

    // ---- load Q (transposed, pre-scaled by 1/sqrt(d) = 0.125)
    #pragma unroll
    for (int it = 0; it < 4; ++it) {
        int idx = tid + it * 256;            // 0..1023 = 64 rows * 16 float4
        int i   = idx >> 4;
        int dc  = (idx & 15) * 4;
        const float4 qv = *(const float4*)(q + bbase + (long)(q0 + i) * rowstride + h * D + dc);
        sQt[(dc + 0) * 68 + i] = qv.x * 0.125f;
        sQt[(dc + 1) * 68 + i] = qv.y * 0.125f;
        sQt[(dc + 2) * 68 + i] = qv.z * 0.125f;
        sQt[(dc + 3) * 68 + i] = qv.w * 0.125f;
    }

    // ---- load K (transposed) and V (straight); zero-fill left pad at j==0
    #pragma unroll
    for (int it = 0; it < 8; ++it) {
        int idx = tid + it * 256;            // 0..2047 = 128 rows * 16 float4
        int m   = idx >> 4;
        int dc  = (idx & 15) * 4;
        int kg  = q0 + m - WSZ;
        float4 kv = make_float4(0.f, 0.f, 0.f, 0.f);
        float4 vv = make_float4(0.f, 0.f, 0.f, 0.f);
        if (kg >= 0) {
            long off = bbase + (long)kg * rowstride + h * D + dc;
            kv = *(const float4*)(k + off);
            vv = *(const float4*)(v + off);
        }
        sKt[(dc + 0) * 132 + m] = kv.x;
        sKt[(dc + 1) * 132 + m] = kv.y;
        sKt[(dc + 2) * 132 + m] = kv.z;
        sKt[(dc + 3) * 132 + m] = kv.w;
        *(float4*)(sV + m * 64 + dc) = vv;
    }
    __syncthreads();

    // ---- QK^T: per-thread tile = 4 queries (i0..i0+3) x 8 keys (m0..m0+7)
    const int i0 = ty * 4;
    const int m0 = tx * 8;
    float accS[4][8];
    #pragma unroll
    for (int r = 0; r < 4; ++r)
        #pragma unroll
        for (int u = 0; u < 8; ++u) accS[r][u] = 0.f;

    #pragma unroll 4
    for (int dd = 0; dd < 64; ++dd) {
        float4 qv = *(float4*)(sQt + dd * 68 + i0);
        float4 k0 = *(float4*)(sKt + dd * 132 + m0);
        float4 k1 = *(float4*)(sKt + dd * 132 + m0 + 4);
        float qq[4] = {qv.x, qv.y, qv.z, qv.w};
        float kk[8] = {k0.x, k0.y, k0.z, k0.w, k1.x, k1.y, k1.z, k1.w};
        #pragma unroll
        for (int r = 0; r < 4; ++r)
            #pragma unroll
            for (int u = 0; u < 8; ++u)
                accS[r][u] += qq[r] * kk[u];
    }

    __syncthreads();   // everyone done reading sKt; sP (alias) writes follow

    // ---- softmax per query row; rows of one ty live in one 16-lane half-warp
    #pragma unroll
    for (int r = 0; r < 4; ++r) {
        const int i = i0 + r;
        bool  val[8];
        float mx = -1e30f;
        #pragma unroll
        for (int u = 0; u < 8; ++u) {
            int m = m0 + u;
            val[u] = (m > i) && (m <= i + WSZ) && (sM[m] != 0.f);
            if (val[u]) mx = fmaxf(mx, accS[r][u]);
        }
        #pragma unroll
        for (int dlt = 1; dlt < 16; dlt <<= 1)
            mx = fmaxf(mx, __shfl_xor_sync(0xffffffffu, mx, dlt));

        float s = 0.f;
        #pragma unroll
        for (int u = 0; u < 8; ++u) {
            float e = val[u] ? __expf(accS[r][u] - mx) : 0.f;
            accS[r][u] = e;
            s += e;
        }
        #pragma unroll
        for (int dlt = 1; dlt < 16; dlt <<= 1)
            s += __shfl_xor_sync(0xffffffffu, s, dlt);

        float inv = (s > 0.f) ? (1.f / s) : 0.f;
        #pragma unroll
        for (int u = 0; u < 8; ++u) accS[r][u] *= inv;

        *(float4*)(sP + i * 132 + m0)     = make_float4(accS[r][0], accS[r][1], accS[r][2], accS[r][3]);
        *(float4*)(sP + i * 132 + m0 + 4) = make_float4(accS[r][4], accS[r][5], accS[r][6], accS[r][7]);
    }
    __syncthreads();

    // ---- P @ V: per-thread tile = 4 queries (i0..i0+3) x 4 dims (dd0..dd0+3)
    // band union for rows i0..i0+3 is m in [i0+1, i0+67]; sP is 0 outside each row's band
    const int dd0 = tx * 4;
    float accO[4][4];
    #pragma unroll
    for (int r = 0; r < 4; ++r)
        #pragma unroll
        for (int c = 0; c < 4; ++c) accO[r][c] = 0.f;

    const int mlo = i0 + 1;
    const int mhi = i0 + 67;   // inclusive, <= 127 always
    for (int m = mlo; m <= mhi; ++m) {
        float4 vv = *(float4*)(sV + m * 64 + dd0);
        float p0 = sP[(i0 + 0) * 132 + m];
        float p1 = sP[(i0 + 1) * 132 + m];
        float p2 = sP[(i0 + 2) * 132 + m];
        float p3 = sP[(i0 + 3) * 132 + m];
        accO[0][0] += p0 * vv.x; accO[0][1] += p0 * vv.y; accO[0][2] += p0 * vv.z; accO[0][3] += p0 * vv.w;
        accO[1][0] += p1 * vv.x; accO[1][1] += p1 * vv.y; accO[1][2] += p1 * vv.z; accO[1][3] += p1 * vv.w;
        accO[2][0] += p2 * vv.x; accO[2][1] += p2 * vv.y; accO[2][2] += p2 * vv.z; accO[2][3] += p2 * vv.w;
        accO[3][0] += p3 * vv.x; accO[3][1] += p3 * vv.y; accO[3][2] += p3 * vv.z; accO[3][3] += p3 * vv.w;
    }

    // ---- epilogue: multiply by query-mask, store
    #pragma unroll
    for (int r = 0; r < 4; ++r) {
        float qmv = sM[WSZ + i0 + r];
        long  off = bbase + (long)(q0 + i0 + r) * rowstride + h * D + dd0;
        float4 ov = make_float4(accO[r][0] * qmv, accO[r][1] * qmv,
                                accO[r][2] * qmv, accO[r][3] * qmv);
        *(float4*)(out + off) = ov;
    }
}

extern "C" void kernel_launch(void* const* d_in, const int* in_sizes, int n_in,
                              void* d_out, int out_size)
{
    const float* q    = (const float*)d_in[0];
    const float* k    = (const float*)d_in[1];
    const float* v    = (const float*)d_in[2];
    const int*   mask = (const int*)d_in[3];

    // shapes: q [b,t,h,64], mask [b,t]; b fixed at 4 per problem spec
    const int BT = in_sizes[3];          // b*t
    const int H  = in_sizes[0] / BT / D; // heads
    const int B  = 4;
    const int T  = BT / B;

    const int smem_bytes = (128 + 64 * 68 + 64 * 132 + 128 * 64) * (int)sizeof(float);
    cudaFuncSetAttribute(lca_kernel, cudaFuncAttributeMaxDynamicSharedMemorySize, smem_bytes);

    dim3 grid(T / WSZ, H, B);
    lca_kernel<<<grid, 256, smem_bytes>>>(q, k, v, mask, (float*)d_out, T, H);
}

// round 3
// speedup vs baseline: 2.4885x; 2.4885x over previous
#include <cuda_runtime.h>
#include <cstdint>

#define WSZ 64
#define DIM 64
#define KSTR 68    // row stride (floats) for Q, K, V tiles in smem
#define PSTR 136   // row stride (floats) for P tile

// SMEM layout (floats):
//   sM  [128]                       mask window
//   sQP [8704]   Q rows [64][68] (dead after A-frag load) ALIASED with P [64][136]
//   sK  [128][68]                   K window, row-major (acts as col-major B)
//   sV  [128][68]                   V window, row-major
// total = 128 + 8704 + 8704 + 8704 = 26240 floats = 104960 B  -> 2 CTAs/SM

__device__ __forceinline__ uint32_t f2tf(float x) {
    uint32_t r; asm("cvt.rna.tf32.f32 %0, %1;" : "=r"(r) : "f"(x)); return r;
}
__device__ __forceinline__ float f2tff(float x) { return __uint_as_float(f2tf(x)); }

__device__ __forceinline__ void mma_tf32(float c[4],
    uint32_t a0, uint32_t a1, uint32_t a2, uint32_t a3,
    uint32_t b0, uint32_t b1)
{
    asm volatile("mma.sync.aligned.m16n8k8.row.col.f32.tf32.tf32.f32 "
        "{%0,%1,%2,%3}, {%4,%5,%6,%7}, {%8,%9}, {%0,%1,%2,%3};"
        : "+f"(c[0]), "+f"(c[1]), "+f"(c[2]), "+f"(c[3])
        : "r"(a0), "r"(a1), "r"(a2), "r"(a3), "r"(b0), "r"(b1));
}

__global__ __launch_bounds__(128)
void lca_kernel(const float* __restrict__ q, const float* __restrict__ k,
                const float* __restrict__ v, const int* __restrict__ mask,
                float* __restrict__ out, int T, int H)
{
    extern __shared__ float sm[];
    float* sM = sm;            // 128
    float* sQ = sm + 128;      // 64*68 (aliased by sP)
    float* sP = sm + 128;      // 64*136
    float* sK = sm + 128 + 8704;
    float* sV = sK + 8704;

    const int j   = blockIdx.x;
    const int h   = blockIdx.y;
    const int b   = blockIdx.z;
    const int tid = threadIdx.x;          // 128 threads
    const int wp  = tid >> 5;             // warp 0..3
    const int ln  = tid & 31;
    const int g   = ln >> 2;              // group 0..7
    const int t   = ln & 3;               // quad lane 0..3

    const long rowstride = (long)H * DIM;
    const long bbase     = (long)b * T * rowstride;
    const int  q0        = j * WSZ;

    // ---- mask window
    if (tid < 128) {
        int kg = q0 + tid - WSZ;
        sM[tid] = (kg >= 0) ? (float)mask[(long)b * T + kg] : 0.0f;
    }

    // ---- Q fill (scaled + tf32-rounded), row-major stride 68
    #pragma unroll
    for (int it = 0; it < 8; ++it) {
        int idx = tid + it * 128;            // 64 rows * 16 float4
        int r   = idx >> 4;
        int c4  = (idx & 15) * 4;
        float4 qv = *(const float4*)(q + bbase + (long)(q0 + r) * rowstride + h * DIM + c4);
        float4 sv = make_float4(f2tff(qv.x * 0.125f), f2tff(qv.y * 0.125f),
                                f2tff(qv.z * 0.125f), f2tff(qv.w * 0.125f));
        *(float4*)(sQ + r * KSTR + c4) = sv;
    }

    // ---- K, V fill (tf32-rounded), zero left pad at j==0
    #pragma unroll
    for (int it = 0; it < 16; ++it) {
        int idx = tid + it * 128;            // 128 rows * 16 float4
        int r   = idx >> 4;
        int c4  = (idx & 15) * 4;
        int kg  = q0 + r - WSZ;
        float4 kv = make_float4(0.f, 0.f, 0.f, 0.f);
        float4 vv = make_float4(0.f, 0.f, 0.f, 0.f);
        if (kg >= 0) {
            long off = bbase + (long)kg * rowstride + h * DIM + c4;
            kv = *(const float4*)(k + off);
            vv = *(const float4*)(v + off);
        }
        *(float4*)(sK + r * KSTR + c4) = make_float4(f2tff(kv.x), f2tff(kv.y), f2tff(kv.z), f2tff(kv.w));
        *(float4*)(sV + r * KSTR + c4) = make_float4(f2tff(vv.x), f2tff(vv.y), f2tff(vv.z), f2tff(vv.w));
    }
    __syncthreads();

    // ---- load Q A-fragments (warp rows: wp*16 + {g, g+8})
    const int ia = wp * 16 + g;       // local row a
    const int ib = ia + 8;            // local row b
    uint32_t aQ[8][4];
    #pragma unroll
    for (int ks = 0; ks < 8; ++ks) {
        int cb = ks * 8 + t;
        aQ[ks][0] = __float_as_uint(sQ[ia * KSTR + cb]);
        aQ[ks][1] = __float_as_uint(sQ[ib * KSTR + cb]);
        aQ[ks][2] = __float_as_uint(sQ[ia * KSTR + cb + 4]);
        aQ[ks][3] = __float_as_uint(sQ[ib * KSTR + cb + 4]);
    }
    __syncthreads();   // everyone done with sQ before sP (alias) is written

    // ---- QK^T on tensor cores: band tiles nt = 2*wp .. 2*wp+9
    float S[10][4];
    #pragma unroll
    for (int x = 0; x < 10; ++x)
        S[x][0] = S[x][1] = S[x][2] = S[x][3] = 0.f;

    #pragma unroll
    for (int x = 0; x < 10; ++x) {
        const int nrow = (2 * wp + x) * 8 + g;      // key row in window
        const float* kr = sK + nrow * KSTR;
        #pragma unroll
        for (int ks = 0; ks < 8; ++ks) {
            uint32_t b0 = __float_as_uint(kr[ks * 8 + t]);
            uint32_t b1 = __float_as_uint(kr[ks * 8 + t + 4]);
            mma_tf32(S[x], aQ[ks][0], aQ[ks][1], aQ[ks][2], aQ[ks][3], b0, b1);
        }
    }

    // ---- softmax (rows ia, ib live in this lane's quad)
    float mxa = -1e30f, mxb = -1e30f;
    unsigned vma = 0, vmb = 0;
    #pragma unroll
    for (int x = 0; x < 10; ++x) {
        int mbase = (2 * wp + x) * 8 + 2 * t;
        #pragma unroll
        for (int u = 0; u < 2; ++u) {
            int m = mbase + u;
            bool mk = (sM[m] != 0.f);
            if ((m > ia) && (m <= ia + WSZ) && mk) { vma |= 1u << (2 * x + u); mxa = fmaxf(mxa, S[x][u]); }
            if ((m > ib) && (m <= ib + WSZ) && mk) { vmb |= 1u << (2 * x + u); mxb = fmaxf(mxb, S[x][2 + u]); }
        }
    }
    mxa = fmaxf(mxa, __shfl_xor_sync(0xffffffffu, mxa, 1));
    mxa = fmaxf(mxa, __shfl_xor_sync(0xffffffffu, mxa, 2));
    mxb = fmaxf(mxb, __shfl_xor_sync(0xffffffffu, mxb, 1));
    mxb = fmaxf(mxb, __shfl_xor_sync(0xffffffffu, mxb, 2));

    float sa = 0.f, sb = 0.f;
    #pragma unroll
    for (int x = 0; x < 10; ++x) {
        #pragma unroll
        for (int u = 0; u < 2; ++u) {
            float pa = ((vma >> (2 * x + u)) & 1u) ? __expf(S[x][u] - mxa) : 0.f;
            float pb = ((vmb >> (2 * x + u)) & 1u) ? __expf(S[x][2 + u] - mxb) : 0.f;
            S[x][u] = pa;  S[x][2 + u] = pb;
            sa += pa;      sb += pb;
        }
    }
    sa += __shfl_xor_sync(0xffffffffu, sa, 1);
    sa += __shfl_xor_sync(0xffffffffu, sa, 2);
    sb += __shfl_xor_sync(0xffffffffu, sb, 1);
    sb += __shfl_xor_sync(0xffffffffu, sb, 2);
    float inva = (sa > 0.f) ? (1.f / sa) : 0.f;
    float invb = (sb > 0.f) ? (1.f / sb) : 0.f;

    // ---- store P (tf32-rounded) to smem, warp-private rows
    #pragma unroll
    for (int x = 0; x < 10; ++x) {
        int col = (2 * wp + x) * 8 + 2 * t;
        *(float2*)(sP + ia * PSTR + col) = make_float2(f2tff(S[x][0] * inva), f2tff(S[x][1] * inva));
        *(float2*)(sP + ib * PSTR + col) = make_float2(f2tff(S[x][2] * invb), f2tff(S[x][3] * invb));
    }
    __syncwarp();

    // ---- P @ V on tensor cores: k-steps ks2 = 2*wp .. 2*wp+9
    float O[8][4];
    #pragma unroll
    for (int nv = 0; nv < 8; ++nv)
        O[nv][0] = O[nv][1] = O[nv][2] = O[nv][3] = 0.f;

    #pragma unroll
    for (int x = 0; x < 10; ++x) {
        const int kb = (2 * wp + x) * 8;
        uint32_t a0 = __float_as_uint(sP[ia * PSTR + kb + t]);
        uint32_t a1 = __float_as_uint(sP[ib * PSTR + kb + t]);
        uint32_t a2 = __float_as_uint(sP[ia * PSTR + kb + t + 4]);
        uint32_t a3 = __float_as_uint(sP[ib * PSTR + kb + t + 4]);
        const float* vr0 = sV + (kb + t) * KSTR;
        const float* vr1 = sV + (kb + t + 4) * KSTR;
        #pragma unroll
        for (int nv = 0; nv < 8; ++nv) {
            uint32_t b0 = __float_as_uint(vr0[nv * 8 + g]);
            uint32_t b1 = __float_as_uint(vr1[nv * 8 + g]);
            mma_tf32(O[nv], a0, a1, a2, a3, b0, b1);
        }
    }

    // ---- epilogue: query-mask, store (float2 per row per n-tile)
    const float qma = sM[WSZ + ia];
    const float qmb = sM[WSZ + ib];
    const long oa = bbase + (long)(q0 + ia) * rowstride + h * DIM;
    const long ob = bbase + (long)(q0 + ib) * rowstride + h * DIM;
    #pragma unroll
    for (int nv = 0; nv < 8; ++nv) {
        int col = nv * 8 + 2 * t;
        *(float2*)(out + oa + col) = make_float2(O[nv][0] * qma, O[nv][1] * qma);
        *(float2*)(out + ob + col) = make_float2(O[nv][2] * qmb, O[nv][3] * qmb);
    }
}

extern "C" void kernel_launch(void* const* d_in, const int* in_sizes, int n_in,
                              void* d_out, int out_size)
{
    const float* q    = (const float*)d_in[0];
    const float* k    = (const float*)d_in[1];
    const float* v    = (const float*)d_in[2];
    const int*   mask = (const int*)d_in[3];

    const int BT = in_sizes[3];            // b*t
    const int H  = in_sizes[0] / BT / DIM; // heads
    const int B  = 4;
    const int T  = BT / B;

    const int smem_bytes = (128 + 8704 + 8704 + 8704) * (int)sizeof(float);
    cudaFuncSetAttribute(lca_kernel, cudaFuncAttributeMaxDynamicSharedMemorySize, smem_bytes);

    dim3 grid(T / WSZ, H, B);
    lca_kernel<<<grid, 128, smem_bytes>>>(q, k, v, mask, (float*)d_out, T, H);
}

// round 4
// speedup vs baseline: 2.8804x; 1.1575x over previous
#include <cuda_runtime.h>
#include <cstdint>

#define WSZ 64
#define DIM 64
#define KSTR 68    // K row stride (floats): banks 4g+t -> conflict-free B-frag loads
#define VSTR 72    // V row stride (floats): banks 8t+g -> conflict-free B-frag loads

// SMEM (floats): sM[128] + sK[128*68] + sV[128*72] = 18048 floats = 72192 B -> 3 CTAs/SM

__device__ __forceinline__ uint32_t f2tf(float x) {
    uint32_t r; asm("cvt.rna.tf32.f32 %0, %1;" : "=r"(r) : "f"(x)); return r;
}
__device__ __forceinline__ float f2tff(float x) { return __uint_as_float(f2tf(x)); }

__device__ __forceinline__ void mma_tf32(float c[4],
    uint32_t a0, uint32_t a1, uint32_t a2, uint32_t a3,
    uint32_t b0, uint32_t b1)
{
    asm volatile("mma.sync.aligned.m16n8k8.row.col.f32.tf32.tf32.f32 "
        "{%0,%1,%2,%3}, {%4,%5,%6,%7}, {%8,%9}, {%0,%1,%2,%3};"
        : "+f"(c[0]), "+f"(c[1]), "+f"(c[2]), "+f"(c[3])
        : "r"(a0), "r"(a1), "r"(a2), "r"(a3), "r"(b0), "r"(b1));
}

__global__ __launch_bounds__(128, 3)
void lca_kernel(const float* __restrict__ q, const float* __restrict__ k,
                const float* __restrict__ v, const int* __restrict__ mask,
                float* __restrict__ out, int T, int H)
{
    extern __shared__ float sm[];
    float* sM = sm;                    // 128
    float* sK = sm + 128;              // 128*68
    float* sV = sK + 128 * KSTR;       // 128*72

    const int j   = blockIdx.x;
    const int h   = blockIdx.y;
    const int b   = blockIdx.z;
    const int tid = threadIdx.x;          // 128 threads
    const int wp  = tid >> 5;             // warp 0..3
    const int ln  = tid & 31;
    const int g   = ln >> 2;              // 0..7
    const int t   = ln & 3;               // 0..3

    const long rowstride = (long)H * DIM;
    const long bbase     = (long)b * T * rowstride;
    const int  q0        = j * WSZ;

    // ---- mask window: sM[m] = mask at key global index q0 + m - 64 (0 if OOB)
    {
        int kg = q0 + tid - WSZ;
        sM[tid] = (kg >= 0) ? (float)mask[(long)b * T + kg] : 0.0f;
    }

    // ---- K, V fill (tf32-rounded), zero left pad at j==0
    #pragma unroll
    for (int it = 0; it < 16; ++it) {
        int idx = tid + it * 128;            // 128 rows * 16 float4
        int r   = idx >> 4;
        int c4  = (idx & 15) * 4;
        int kg  = q0 + r - WSZ;
        float4 kv = make_float4(0.f, 0.f, 0.f, 0.f);
        float4 vv = make_float4(0.f, 0.f, 0.f, 0.f);
        if (kg >= 0) {
            long off = bbase + (long)kg * rowstride + h * DIM + c4;
            kv = *(const float4*)(k + off);
            vv = *(const float4*)(v + off);
        }
        *(float4*)(sK + r * KSTR + c4) = make_float4(f2tff(kv.x), f2tff(kv.y), f2tff(kv.z), f2tff(kv.w));
        *(float4*)(sV + r * VSTR + c4) = make_float4(f2tff(vv.x), f2tff(vv.y), f2tff(vv.z), f2tff(vv.w));
    }

    // ---- Q A-fragments straight from gmem (rows ia, ib; scaled + tf32)
    const int ia = wp * 16 + g;
    const int ib = ia + 8;
    const float* qra = q + bbase + (long)(q0 + ia) * rowstride + h * DIM;
    const float* qrb = qra + 8 * rowstride;
    uint32_t aQ[8][4];
    #pragma unroll
    for (int ks = 0; ks < 8; ++ks) {
        aQ[ks][0] = f2tf(qra[ks * 8 + t]     * 0.125f);
        aQ[ks][1] = f2tf(qrb[ks * 8 + t]     * 0.125f);
        aQ[ks][2] = f2tf(qra[ks * 8 + t + 4] * 0.125f);
        aQ[ks][3] = f2tf(qrb[ks * 8 + t + 4] * 0.125f);
    }

    __syncthreads();   // the only block-wide sync

    // ---- QK^T on tensor cores: band tiles x = 0..9 (key tiles 2wp..2wp+9)
    float S[10][4];
    #pragma unroll
    for (int x = 0; x < 10; ++x)
        S[x][0] = S[x][1] = S[x][2] = S[x][3] = 0.f;

    #pragma unroll
    for (int x = 0; x < 10; ++x) {
        const float* kr = sK + ((2 * wp + x) * 8 + g) * KSTR;
        #pragma unroll
        for (int ks = 0; ks < 8; ++ks) {
            uint32_t b0 = __float_as_uint(kr[ks * 8 + t]);
            uint32_t b1 = __float_as_uint(kr[ks * 8 + t + 4]);
            mma_tf32(S[x], aQ[ks][0], aQ[ks][1], aQ[ks][2], aQ[ks][3], b0, b1);
        }
    }

    // ---- softmax (rows ia, ib live in this lane's quad)
    float mxa = -1e30f, mxb = -1e30f;
    unsigned vma = 0, vmb = 0;
    #pragma unroll
    for (int x = 0; x < 10; ++x) {
        int mbase = (2 * wp + x) * 8 + 2 * t;
        #pragma unroll
        for (int u = 0; u < 2; ++u) {
            int m = mbase + u;
            bool mk = (sM[m] != 0.f);
            if ((m > ia) && (m <= ia + WSZ) && mk) { vma |= 1u << (2 * x + u); mxa = fmaxf(mxa, S[x][u]); }
            if ((m > ib) && (m <= ib + WSZ) && mk) { vmb |= 1u << (2 * x + u); mxb = fmaxf(mxb, S[x][2 + u]); }
        }
    }
    mxa = fmaxf(mxa, __shfl_xor_sync(0xffffffffu, mxa, 1));
    mxa = fmaxf(mxa, __shfl_xor_sync(0xffffffffu, mxa, 2));
    mxb = fmaxf(mxb, __shfl_xor_sync(0xffffffffu, mxb, 1));
    mxb = fmaxf(mxb, __shfl_xor_sync(0xffffffffu, mxb, 2));

    float sa = 0.f, sb = 0.f;
    #pragma unroll
    for (int x = 0; x < 10; ++x) {
        #pragma unroll
        for (int u = 0; u < 2; ++u) {
            float pa = ((vma >> (2 * x + u)) & 1u) ? __expf(S[x][u] - mxa) : 0.f;
            float pb = ((vmb >> (2 * x + u)) & 1u) ? __expf(S[x][2 + u] - mxb) : 0.f;
            S[x][u] = pa;  S[x][2 + u] = pb;
            sa += pa;      sb += pb;
        }
    }
    sa += __shfl_xor_sync(0xffffffffu, sa, 1);
    sa += __shfl_xor_sync(0xffffffffu, sa, 2);
    sb += __shfl_xor_sync(0xffffffffu, sb, 1);
    sb += __shfl_xor_sync(0xffffffffu, sb, 2);
    const float inva = (sa > 0.f) ? (1.f / sa) : 0.f;
    const float invb = (sb > 0.f) ? (1.f / sb) : 0.f;

    #pragma unroll
    for (int x = 0; x < 10; ++x) {
        S[x][0] *= inva;  S[x][1] *= inva;
        S[x][2] *= invb;  S[x][3] *= invb;
    }

    // ---- P @ V: A-fragments of P built by quad-local shuffles (no smem P)
    float O[8][4];
    #pragma unroll
    for (int nv = 0; nv < 8; ++nv)
        O[nv][0] = O[nv][1] = O[nv][2] = O[nv][3] = 0.f;

    const int  s0 = (ln & ~3) | (t >> 1);   // quad lane holding col t (pair t/2)
    const int  s1 = s0 + 2;                 // quad lane holding col t+4
    const bool hi = (t & 1);

    #pragma unroll
    for (int x = 0; x < 10; ++x) {
        // row ia fragment regs a0 (col t), a2 (col t+4)
        float w0 = __shfl_sync(0xffffffffu, S[x][0], s0);
        float w1 = __shfl_sync(0xffffffffu, S[x][1], s0);
        float w2 = __shfl_sync(0xffffffffu, S[x][0], s1);
        float w3 = __shfl_sync(0xffffffffu, S[x][1], s1);
        uint32_t a0 = f2tf(hi ? w1 : w0);
        uint32_t a2 = f2tf(hi ? w3 : w2);
        // row ib fragment regs a1 (col t), a3 (col t+4)
        float y0 = __shfl_sync(0xffffffffu, S[x][2], s0);
        float y1 = __shfl_sync(0xffffffffu, S[x][3], s0);
        float y2 = __shfl_sync(0xffffffffu, S[x][2], s1);
        float y3 = __shfl_sync(0xffffffffu, S[x][3], s1);
        uint32_t a1 = f2tf(hi ? y1 : y0);
        uint32_t a3 = f2tf(hi ? y3 : y2);

        const int kb = (2 * wp + x) * 8;
        const float* vr0 = sV + (kb + t) * VSTR;
        const float* vr1 = vr0 + 4 * VSTR;
        #pragma unroll
        for (int nv = 0; nv < 8; ++nv) {
            uint32_t b0 = __float_as_uint(vr0[nv * 8 + g]);
            uint32_t b1 = __float_as_uint(vr1[nv * 8 + g]);
            mma_tf32(O[nv], a0, a1, a2, a3, b0, b1);
        }
    }

    // ---- epilogue: query-mask, store
    const float qma = sM[WSZ + ia];
    const float qmb = sM[WSZ + ib];
    const long oa = bbase + (long)(q0 + ia) * rowstride + h * DIM;
    const long ob = bbase + (long)(q0 + ib) * rowstride + h * DIM;
    #pragma unroll
    for (int nv = 0; nv < 8; ++nv) {
        int col = nv * 8 + 2 * t;
        *(float2*)(out + oa + col) = make_float2(O[nv][0] * qma, O[nv][1] * qma);
        *(float2*)(out + ob + col) = make_float2(O[nv][2] * qmb, O[nv][3] * qmb);
    }
}

extern "C" void kernel_launch(void* const* d_in, const int* in_sizes, int n_in,
                              void* d_out, int out_size)
{
    const float* q    = (const float*)d_in[0];
    const float* k    = (const float*)d_in[1];
    const float* v    = (const float*)d_in[2];
    const int*   mask = (const int*)d_in[3];

    const int BT = in_sizes[3];            // b*t
    const int H  = in_sizes[0] / BT / DIM; // heads
    const int B  = 4;
    const int T  = BT / B;

    const int smem_bytes = (128 + 128 * KSTR + 128 * VSTR) * (int)sizeof(float);
    cudaFuncSetAttribute(lca_kernel, cudaFuncAttributeMaxDynamicSharedMemorySize, smem_bytes);

    dim3 grid(T / WSZ, H, B);
    lca_kernel<<<grid, 128, smem_bytes>>>(q, k, v, mask, (float*)d_out, T, H);
}

// round 5
// speedup vs baseline: 4.6536x; 1.6156x over previous
#include <cuda_runtime.h>
#include <cuda_fp16.h>
#include <cstdint>

#define WSZ 64
#define DIM 64
#define KVSTR 72   // K/V row stride in halves (36 words -> ldmatrix row bases 4r mod 32, conflict-free)

// SMEM: sM float[128] (512B) + sK half[128*72] (18432B) + sV half[128*72] (18432B) = 37376B -> 4 CTAs/SM

__device__ __forceinline__ uint32_t pack2h(float x, float y) {
    __half2 h = __floats2half2_rn(x, y);
    return *reinterpret_cast<uint32_t*>(&h);
}

__device__ __forceinline__ void mma_f16(float c[4],
    uint32_t a0, uint32_t a1, uint32_t a2, uint32_t a3, uint32_t b0, uint32_t b1)
{
    asm volatile("mma.sync.aligned.m16n8k16.row.col.f32.f16.f16.f32 "
        "{%0,%1,%2,%3}, {%4,%5,%6,%7}, {%8,%9}, {%0,%1,%2,%3};"
        : "+f"(c[0]), "+f"(c[1]), "+f"(c[2]), "+f"(c[3])
        : "r"(a0), "r"(a1), "r"(a2), "r"(a3), "r"(b0), "r"(b1));
}

__device__ __forceinline__ void ldsm_x4(uint32_t& r0, uint32_t& r1, uint32_t& r2, uint32_t& r3, uint32_t addr) {
    asm volatile("ldmatrix.sync.aligned.m8n8.x4.shared.b16 {%0,%1,%2,%3}, [%4];"
        : "=r"(r0), "=r"(r1), "=r"(r2), "=r"(r3) : "r"(addr));
}
__device__ __forceinline__ void ldsm_x4_t(uint32_t& r0, uint32_t& r1, uint32_t& r2, uint32_t& r3, uint32_t addr) {
    asm volatile("ldmatrix.sync.aligned.m8n8.x4.trans.shared.b16 {%0,%1,%2,%3}, [%4];"
        : "=r"(r0), "=r"(r1), "=r"(r2), "=r"(r3) : "r"(addr));
}

__global__ __launch_bounds__(128, 4)
void lca_kernel(const float* __restrict__ q, const float* __restrict__ k,
                const float* __restrict__ v, const int* __restrict__ mask,
                float* __restrict__ out, int T, int H)
{
    extern __shared__ char smraw[];
    float*  sM = (float*)smraw;                       // 128 floats
    __half* sK = (__half*)(smraw + 512);              // 128 x 72
    __half* sV = sK + 128 * KVSTR;                    // 128 x 72

    const int j   = blockIdx.x;
    const int h   = blockIdx.y;
    const int b   = blockIdx.z;
    const int tid = threadIdx.x;          // 128 threads
    const int wp  = tid >> 5;
    const int ln  = tid & 31;
    const int g   = ln >> 2;              // 0..7
    const int t   = ln & 3;               // 0..3

    const long rowstride = (long)H * DIM;
    const long bbase     = (long)b * T * rowstride;
    const int  q0        = j * WSZ;

    // ---- mask window
    {
        int kg = q0 + tid - WSZ;
        sM[tid] = (kg >= 0) ? (float)mask[(long)b * T + kg] : 0.0f;
    }

    // ---- K, V fill as fp16 (zero left pad at j==0)
    #pragma unroll
    for (int it = 0; it < 16; ++it) {
        int idx = tid + it * 128;            // 128 rows * 16 float4
        int r   = idx >> 4;
        int c4  = (idx & 15) * 4;
        int kg  = q0 + r - WSZ;
        float4 kv = make_float4(0.f, 0.f, 0.f, 0.f);
        float4 vv = make_float4(0.f, 0.f, 0.f, 0.f);
        if (kg >= 0) {
            long off = bbase + (long)kg * rowstride + h * DIM + c4;
            kv = *(const float4*)(k + off);
            vv = *(const float4*)(v + off);
        }
        *(uint2*)(sK + r * KVSTR + c4) = make_uint2(pack2h(kv.x, kv.y), pack2h(kv.z, kv.w));
        *(uint2*)(sV + r * KVSTR + c4) = make_uint2(pack2h(vv.x, vv.y), pack2h(vv.z, vv.w));
    }

    // ---- Q A-fragments from gmem (rows ia, ib), scaled by 1/8, fp16
    const int ia = wp * 16 + g;
    const int ib = ia + 8;
    const float* qra = q + bbase + (long)(q0 + ia) * rowstride + h * DIM;
    const float* qrb = qra + 8 * rowstride;
    uint32_t aQ[4][4];
    #pragma unroll
    for (int ks = 0; ks < 4; ++ks) {
        const int k0 = ks * 16;
        float2 a = *(const float2*)(qra + k0 + 2 * t);
        float2 bq = *(const float2*)(qrb + k0 + 2 * t);
        float2 c = *(const float2*)(qra + k0 + 2 * t + 8);
        float2 d = *(const float2*)(qrb + k0 + 2 * t + 8);
        aQ[ks][0] = pack2h(a.x * 0.125f, a.y * 0.125f);
        aQ[ks][1] = pack2h(bq.x * 0.125f, bq.y * 0.125f);
        aQ[ks][2] = pack2h(c.x * 0.125f, c.y * 0.125f);
        aQ[ks][3] = pack2h(d.x * 0.125f, d.y * 0.125f);
    }

    __syncthreads();

    const uint32_t sK_u = (uint32_t)__cvta_generic_to_shared(sK);
    const uint32_t sV_u = (uint32_t)__cvta_generic_to_shared(sV);

    // ldmatrix lane decomposition (shared by QK and PV address formation)
    const int r8  = ln & 7;             // row within 8x8 tile
    const int hi8 = (ln >> 3) & 1;      // tile pair selector
    const int hi16 = ln >> 4;           // tile quad selector

    // ---- QK^T: band tiles x = 0..9; x4 ldmatrix covers n-tiles {2e, 2e+1}
    float S[10][4];
    #pragma unroll
    for (int x = 0; x < 10; ++x)
        S[x][0] = S[x][1] = S[x][2] = S[x][3] = 0.f;

    #pragma unroll
    for (int e = 0; e < 5; ++e) {
        // key row for this lane's tile: tiles 0,1 -> n-group 0; tiles 2,3 -> +8
        const int key  = (2 * wp + 2 * e) * 8 + (hi16 << 3) + r8;
        const uint32_t rowaddr = sK_u + (uint32_t)(key * KVSTR) * 2;
        #pragma unroll
        for (int ks = 0; ks < 4; ++ks) {
            const int hoff = ks * 16 + (hi8 << 3);   // tiles 0,2 -> k0; tiles 1,3 -> k0+8
            uint32_t b0, b1, b2, b3;
            ldsm_x4(b0, b1, b2, b3, rowaddr + (uint32_t)hoff * 2);
            mma_f16(S[2 * e],     aQ[ks][0], aQ[ks][1], aQ[ks][2], aQ[ks][3], b0, b1);
            mma_f16(S[2 * e + 1], aQ[ks][0], aQ[ks][1], aQ[ks][2], aQ[ks][3], b2, b3);
        }
    }

    // ---- softmax (rows ia, ib live in this lane's quad)
    float mxa = -1e30f, mxb = -1e30f;
    unsigned vma = 0, vmb = 0;
    #pragma unroll
    for (int x = 0; x < 10; ++x) {
        int mbase = (2 * wp + x) * 8 + 2 * t;
        #pragma unroll
        for (int u = 0; u < 2; ++u) {
            int m = mbase + u;
            bool mk = (sM[m] != 0.f);
            if ((m > ia) && (m <= ia + WSZ) && mk) { vma |= 1u << (2 * x + u); mxa = fmaxf(mxa, S[x][u]); }
            if ((m > ib) && (m <= ib + WSZ) && mk) { vmb |= 1u << (2 * x + u); mxb = fmaxf(mxb, S[x][2 + u]); }
        }
    }
    mxa = fmaxf(mxa, __shfl_xor_sync(0xffffffffu, mxa, 1));
    mxa = fmaxf(mxa, __shfl_xor_sync(0xffffffffu, mxa, 2));
    mxb = fmaxf(mxb, __shfl_xor_sync(0xffffffffu, mxb, 1));
    mxb = fmaxf(mxb, __shfl_xor_sync(0xffffffffu, mxb, 2));

    float sa = 0.f, sb = 0.f;
    #pragma unroll
    for (int x = 0; x < 10; ++x) {
        #pragma unroll
        for (int u = 0; u < 2; ++u) {
            float pa = ((vma >> (2 * x + u)) & 1u) ? __expf(S[x][u] - mxa) : 0.f;
            float pb = ((vmb >> (2 * x + u)) & 1u) ? __expf(S[x][2 + u] - mxb) : 0.f;
            S[x][u] = pa;  S[x][2 + u] = pb;
            sa += pa;      sb += pb;
        }
    }
    sa += __shfl_xor_sync(0xffffffffu, sa, 1);
    sa += __shfl_xor_sync(0xffffffffu, sa, 2);
    sb += __shfl_xor_sync(0xffffffffu, sb, 1);
    sb += __shfl_xor_sync(0xffffffffu, sb, 2);
    const float inva = (sa > 0.f) ? (1.f / sa) : 0.f;
    const float invb = (sb > 0.f) ? (1.f / sb) : 0.f;

    // ---- P @ V: A-frags are this lane's own S values (m16n8k16 A == two m16n8k8 C frags)
    float O[8][4];
    #pragma unroll
    for (int nv = 0; nv < 8; ++nv)
        O[nv][0] = O[nv][1] = O[nv][2] = O[nv][3] = 0.f;

    #pragma unroll
    for (int s = 0; s < 5; ++s) {
        const uint32_t pa0 = pack2h(S[2 * s][0] * inva,     S[2 * s][1] * inva);
        const uint32_t pa1 = pack2h(S[2 * s][2] * invb,     S[2 * s][3] * invb);
        const uint32_t pa2 = pack2h(S[2 * s + 1][0] * inva, S[2 * s + 1][1] * inva);
        const uint32_t pa3 = pack2h(S[2 * s + 1][2] * invb, S[2 * s + 1][3] * invb);

        // V tile rows (keys): tiles 0,2 -> +0..7 ; tiles 1,3 -> +8..15
        const int key = (2 * wp + 2 * s) * 8 + (hi8 << 3) + r8;
        const uint32_t rowaddr = sV_u + (uint32_t)(key * KVSTR) * 2;
        #pragma unroll
        for (int nd = 0; nd < 4; ++nd) {
            const int hoff = nd * 16 + (hi16 << 3);  // tiles 0,1 -> n0; tiles 2,3 -> n0+8
            uint32_t b0, b1, b2, b3;
            ldsm_x4_t(b0, b1, b2, b3, rowaddr + (uint32_t)hoff * 2);
            mma_f16(O[2 * nd],     pa0, pa1, pa2, pa3, b0, b1);
            mma_f16(O[2 * nd + 1], pa0, pa1, pa2, pa3, b2, b3);
        }
    }

    // ---- epilogue: query-mask, store
    const float qma = sM[WSZ + ia];
    const float qmb = sM[WSZ + ib];
    const long oa = bbase + (long)(q0 + ia) * rowstride + h * DIM;
    const long ob = bbase + (long)(q0 + ib) * rowstride + h * DIM;
    #pragma unroll
    for (int nv = 0; nv < 8; ++nv) {
        int col = nv * 8 + 2 * t;
        *(float2*)(out + oa + col) = make_float2(O[nv][0] * qma, O[nv][1] * qma);
        *(float2*)(out + ob + col) = make_float2(O[nv][2] * qmb, O[nv][3] * qmb);
    }
}

extern "C" void kernel_launch(void* const* d_in, const int* in_sizes, int n_in,
                              void* d_out, int out_size)
{
    const float* q    = (const float*)d_in[0];
    const float* k    = (const float*)d_in[1];
    const float* v    = (const float*)d_in[2];
    const int*   mask = (const int*)d_in[3];

    const int BT = in_sizes[3];            // b*t
    const int H  = in_sizes[0] / BT / DIM; // heads
    const int B  = 4;
    const int T  = BT / B;

    const int smem_bytes = 512 + 2 * 128 * KVSTR * (int)sizeof(__half);
    cudaFuncSetAttribute(lca_kernel, cudaFuncAttributeMaxDynamicSharedMemorySize, smem_bytes);

    dim3 grid(T / WSZ, H, B);
    lca_kernel<<<grid, 128, smem_bytes>>>(q, k, v, mask, (float*)d_out, T, H);
}